// round 1
// baseline (speedup 1.0000x reference)
#include <cuda_runtime.h>

#define BLKX 32
#define BLKY 16
#define PX 4
#define TILE_W (BLKX*PX)   // 128 outputs wide per block
#define TILE_H BLKY        // 16 output rows per block

// Partial sums: kz=3 kernel uses slots [0,512), kz=5 uses [512,2560)
__device__ double g_part[2560];

template<int KZ>
__global__ void __launch_bounds__(512) affine_kernel(const float* __restrict__ in,
                                                     int H, int W, double scale,
                                                     int part_off)
{
    constexpr int SMW = 132;                 // padded row (floats), 16B-aligned rows
    constexpr int SMH = TILE_H + KZ - 1;
    constexpr int NC  = KZ + PX - 1;         // columns of partial sums per thread
    __shared__ __align__(16) float tile[SMH * SMW];

    const int img = blockIdx.z;
    const int gy0 = blockIdx.y * TILE_H;
    const int gx0 = blockIdx.x * TILE_W;
    const int tid = threadIdx.y * BLKX + threadIdx.x;
    const float* src = in + (size_t)img * H * W;

    // Cooperative tile load (coalesced, zero-fill out of range)
    for (int idx = tid; idx < SMH * SMW; idx += 512) {
        int r = idx / SMW, c = idx - r * SMW;
        int y = gy0 + r, x = gx0 + c;
        tile[idx] = (y < H && x < W) ? src[y * W + x] : 0.f;
    }
    __syncthreads();

    const int lr = threadIdx.y;
    const int lc = threadIdx.x * PX;
    constexpr float M = (KZ - 1) * 0.5f;

    // Vertical (over patch rows) column sums: box, row-weighted, squares
    float c0[NC], c1[NC], c2[NC];
#pragma unroll
    for (int x = 0; x < NC; x++) { c0[x] = 0.f; c1[x] = 0.f; c2[x] = 0.f; }

#pragma unroll
    for (int a = 0; a < KZ; a++) {
        const float4 va = *reinterpret_cast<const float4*>(&tile[(lr + a) * SMW + lc]);
        const float4 vb = *reinterpret_cast<const float4*>(&tile[(lr + a) * SMW + lc + 4]);
        const float f[8] = {va.x, va.y, va.z, va.w, vb.x, vb.y, vb.z, vb.w};
        const float wa = (float)a - M;
#pragma unroll
        for (int x = 0; x < NC; x++) {
            c0[x] += f[x];
            c1[x] = fmaf(wa, f[x], c1[x]);
            c2[x] = fmaf(f[x], f[x], c2[x]);
        }
    }

    const int outH = H - KZ + 1, outW = W - KZ + 1;
    constexpr float inv_box = 1.f / (float)(KZ * KZ);
    constexpr float inv_lin = 12.f / (float)(KZ * KZ * (KZ * KZ - 1));
    const bool rowvalid = (gy0 + lr) < outH;

    float acc = 0.f;
#pragma unroll
    for (int k = 0; k < PX; k++) {
        float s0 = 0.f, sr = 0.f, sc = 0.f, s2 = 0.f;
#pragma unroll
        for (int c = 0; c < KZ; c++) {
            s0 += c0[k + c];
            sr += c1[k + c];
            s2 += c2[k + c];
            sc = fmaf((float)c - M, c0[k + c], sc);
        }
        const float q = s2 - s0 * s0 * inv_box - (sr * sr + sc * sc) * inv_lin;
        if (rowvalid && (gx0 + lc + k) < outW) acc += q;
    }

    // Block reduction (float), deterministic slot write (double)
#pragma unroll
    for (int o = 16; o > 0; o >>= 1) acc += __shfl_down_sync(0xffffffffu, acc, o);
    __shared__ float wsum[16];
    if ((tid & 31) == 0) wsum[tid >> 5] = acc;
    __syncthreads();
    if (tid < 32) {
        float v = (tid < 16) ? wsum[tid] : 0.f;
#pragma unroll
        for (int o = 8; o > 0; o >>= 1) v += __shfl_down_sync(0xffffffffu, v, o);
        if (tid == 0) {
            int bid = (blockIdx.z * gridDim.y + blockIdx.y) * gridDim.x + blockIdx.x;
            g_part[part_off + bid] = (double)v * scale;
        }
    }
}

__global__ void finalize_kernel(float* __restrict__ out, int n)
{
    double s = 0.0;
    for (int i = threadIdx.x; i < n; i += 256) s += g_part[i];
#pragma unroll
    for (int o = 16; o > 0; o >>= 1) s += __shfl_down_sync(0xffffffffu, s, o);
    __shared__ double ws[8];
    if ((threadIdx.x & 31) == 0) ws[threadIdx.x >> 5] = s;
    __syncthreads();
    if (threadIdx.x < 32) {
        double v = (threadIdx.x < 8) ? ws[threadIdx.x] : 0.0;
#pragma unroll
        for (int o = 4; o > 0; o >>= 1) v += __shfl_down_sync(0xffffffffu, v, o);
        if (threadIdx.x == 0) out[0] = (float)v;
    }
}

extern "C" void kernel_launch(void* const* d_in, const int* in_sizes, int n_in,
                              void* d_out, int out_size)
{
    const float* flow0 = (const float*)d_in[0];  // (32,2,128,128)
    const float* flow1 = (const float*)d_in[1];  // (32,2,256,256)
    float* out = (float*)d_out;

    dim3 b(BLKX, BLKY);

    // kz=3 on flow0: outH=outW=126; mean denom 32*126*126 per channel
    {
        dim3 g((126 + TILE_W - 1) / TILE_W, (126 + TILE_H - 1) / TILE_H, 64); // 1 x 8 x 64 = 512
        affine_kernel<3><<<g, b>>>(flow0, 128, 128, 1.0 / (32.0 * 126.0 * 126.0), 0);
    }
    // kz=5 on flow1: outH=outW=252; mean denom 32*252*252 per channel
    {
        dim3 g((252 + TILE_W - 1) / TILE_W, (252 + TILE_H - 1) / TILE_H, 64); // 2 x 16 x 64 = 2048
        affine_kernel<5><<<g, b>>>(flow1, 256, 256, 1.0 / (32.0 * 252.0 * 252.0), 512);
    }
    finalize_kernel<<<1, 256>>>(out, 2560);
}

// round 3
// speedup vs baseline: 1.7720x; 1.7720x over previous
#include <cuda_runtime.h>

// ---- problem geometry ----
// kz=3 : 64 images (32 batch x 2 chan) of 128x128, out 126x126
// kz=5 : 64 images of 256x256, out 252x252

#define B3_BLOCKS 88          // 64 img * 32 colgroups * 11 chunks = 22528 thr = 88 * 256
#define T5_THREADS 68544      // 64 img * 63 colgroups * 17 chunks
#define B5_BLOCKS 268         // ceil(68544/256)
#define NBLOCKS (B3_BLOCKS + B5_BLOCKS)   // 356

__device__ double g_part[NBLOCKS];
__device__ int    g_count;    // zero-init; reset by finalizing block (graph-replay safe)

// Load 8 contiguous floats at p (second half zeroed if !xfull) and compute
// horizontal window stats (sum, col-weighted sum, sum of squares) for the
// 4 windows starting at offsets 0..3.
template<int KZ>
__device__ __forceinline__ void load_hstats(const float* __restrict__ p, bool xfull,
                                            float (&o0)[4], float (&oc)[4], float (&o2)[4])
{
    constexpr float M = (KZ - 1) * 0.5f;
    float f[8];
    float4 va = *reinterpret_cast<const float4*>(p);
    f[0] = va.x; f[1] = va.y; f[2] = va.z; f[3] = va.w;
    if (xfull) {
        float4 vb = *reinterpret_cast<const float4*>(p + 4);
        f[4] = vb.x; f[5] = vb.y; f[6] = vb.z; f[7] = vb.w;
    } else {
        f[4] = 0.f; f[5] = 0.f; f[6] = 0.f; f[7] = 0.f;
    }
#pragma unroll
    for (int k = 0; k < 4; k++) {
        float s0 = 0.f, sc = 0.f, s2 = 0.f;
#pragma unroll
        for (int c = 0; c < KZ; c++) {
            float v = f[k + c];
            s0 += v;
            s2 = fmaf(v, v, s2);
            sc = fmaf((float)c - M, v, sc);
        }
        o0[k] = s0; oc[k] = sc; o2[k] = s2;
    }
}

// Per-thread: 4 output columns (x0..x0+3), R output rows starting at oy0.
// Register ring of KZ rows of horizontal stats.
template<int KZ, int R, int CG, int CH>
__device__ __forceinline__ float thread_work(const float* __restrict__ src0,
                                             int H, int W, int t)
{
    constexpr int PERIMG = CG * CH;
    const int img   = t / PERIMG;
    int rem         = t - img * PERIMG;
    const int chunk = rem / CG;
    const int cg    = rem - chunk * CG;
    const int x0    = cg * 4;
    const int oy0   = chunk * R;
    const float* __restrict__ src = src0 + (size_t)img * H * W;

    const int outH = H - KZ + 1;
    const int outW = W - KZ + 1;
    constexpr float M  = (KZ - 1) * 0.5f;
    constexpr float ib = 1.f / (float)(KZ * KZ);
    constexpr float il = 12.f / (float)(KZ * KZ * (KZ * KZ - 1));

    const bool xfull = (x0 + 8) <= W;

    float r0[KZ][4], rc[KZ][4], r2[KZ][4];
    float acc = 0.f;

    // warmup: input rows oy0 .. oy0+KZ-2 into slots 0..KZ-2
#pragma unroll
    for (int p = 0; p < KZ - 1; p++) {
        int yy = oy0 + p; yy = yy < (H - 1) ? yy : (H - 1);
        load_hstats<KZ>(src + (size_t)yy * W + x0, xfull, r0[p], rc[p], r2[p]);
    }

    // main: output row oy0+i uses input rows oy0+i .. oy0+i+KZ-1
    // input row (oy0+j) lives in ring slot j%KZ (constant after full unroll)
#pragma unroll
    for (int i = 0; i < R; i++) {
        {
            int yy = oy0 + i + KZ - 1; yy = yy < (H - 1) ? yy : (H - 1);
            constexpr int dummy = 0; (void)dummy;
            const int slot = (i + KZ - 1) % KZ;
            load_hstats<KZ>(src + (size_t)yy * W + x0, xfull, r0[slot], rc[slot], r2[slot]);
        }
        const bool yok = (oy0 + i) < outH;
        float q4 = 0.f;
#pragma unroll
        for (int k = 0; k < 4; k++) {
            float S0 = 0.f, S2 = 0.f, Sc = 0.f, Sr = 0.f;
#pragma unroll
            for (int a = 0; a < KZ; a++) {
                const int s = (i + a) % KZ;
                S0 += r0[s][k];
                S2 += r2[s][k];
                Sc += rc[s][k];
                Sr = fmaf((float)a - M, r0[s][k], Sr);
            }
            float q = S2 - S0 * S0 * ib - (Sr * Sr + Sc * Sc) * il;
            if (yok && (x0 + k) < outW) q4 += q;
        }
        acc += q4;
    }
    return acc;
}

__global__ void __launch_bounds__(256) fused_kernel(const float* __restrict__ f0,
                                                    const float* __restrict__ f1,
                                                    float* __restrict__ out)
{
    const int tid = threadIdx.x;
    float acc = 0.f;
    double scale;

    if (blockIdx.x < B3_BLOCKS) {
        const int t = blockIdx.x * 256 + tid;          // exact: 88*256 = 22528
        acc = thread_work<3, 12, 32, 11>(f0, 128, 128, t);
        scale = 1.0 / (32.0 * 126.0 * 126.0);
    } else {
        const int t = (blockIdx.x - B3_BLOCKS) * 256 + tid;
        if (t < T5_THREADS)
            acc = thread_work<5, 15, 63, 17>(f1, 256, 256, t);
        scale = 1.0 / (32.0 * 252.0 * 252.0);
    }

    // block reduction (float, deterministic)
#pragma unroll
    for (int o = 16; o > 0; o >>= 1) acc += __shfl_down_sync(0xffffffffu, acc, o);
    __shared__ float wsum[8];
    __shared__ bool  lastflag;
    if ((tid & 31) == 0) wsum[tid >> 5] = acc;
    __syncthreads();
    if (tid < 32) {
        float v = (tid < 8) ? wsum[tid] : 0.f;
#pragma unroll
        for (int o = 4; o > 0; o >>= 1) v += __shfl_down_sync(0xffffffffu, v, o);
        if (tid == 0) {
            g_part[blockIdx.x] = (double)v * scale;
            __threadfence();
            int done = atomicAdd(&g_count, 1);
            lastflag = (done == NBLOCKS - 1);
        }
    }
    __syncthreads();

    // last arriving block finalizes (deterministic fixed-order sum), resets counter
    if (lastflag) {
        __threadfence();
        double s = 0.0;
        for (int i = tid; i < NBLOCKS; i += 256) s += g_part[i];
#pragma unroll
        for (int o = 16; o > 0; o >>= 1) s += __shfl_down_sync(0xffffffffu, s, o);
        __shared__ double ws[8];
        if ((tid & 31) == 0) ws[tid >> 5] = s;
        __syncthreads();
        if (tid < 32) {
            double v = (tid < 8) ? ws[tid] : 0.0;
#pragma unroll
            for (int o = 4; o > 0; o >>= 1) v += __shfl_down_sync(0xffffffffu, v, o);
            if (tid == 0) {
                out[0] = (float)v;
                g_count = 0;   // reset for next graph replay
            }
        }
    }
}

extern "C" void kernel_launch(void* const* d_in, const int* in_sizes, int n_in,
                              void* d_out, int out_size)
{
    const float* flow0 = (const float*)d_in[0];  // (32,2,128,128)
    const float* flow1 = (const float*)d_in[1];  // (32,2,256,256)
    if (n_in >= 2 && in_sizes[0] > in_sizes[1]) { // robustness: identify by size
        const float* t = flow0; flow0 = flow1; flow1 = t;
    }
    fused_kernel<<<NBLOCKS, 256>>>(flow0, flow1, (float*)d_out);
}

// round 4
// speedup vs baseline: 2.2800x; 1.2867x over previous
#include <cuda_runtime.h>

// ---- geometry ----
// kz=3 : 64 images 128x128, out 126x126 ; CG=32 colgroups(x4), CH=9 chunks x R=14 rows
// kz=5 : 64 images 256x256, out 252x252 ; CG=63, CH=18 x R=14
#define B3_BLOCKS 72           // 64*32*9 = 18432 = 72*256
#define T5_THREADS 72576       // 64*63*18
#define B5_BLOCKS 284
#define NBLOCKS (B3_BLOCKS + B5_BLOCKS)   // 356

__device__ double g_part[NBLOCKS];
__device__ int    g_count;

typedef unsigned long long u64;

__device__ __forceinline__ u64 pack2(float lo, float hi) {
    u64 r; asm("mov.b64 %0, {%1,%2};" : "=l"(r) : "f"(lo), "f"(hi)); return r;
}
__device__ __forceinline__ u64 fma2(u64 a, u64 b, u64 c) {
    u64 d; asm("fma.rn.f32x2 %0, %1, %2, %3;" : "=l"(d) : "l"(a), "l"(b), "l"(c)); return d;
}
__device__ __forceinline__ u64 add2(u64 a, u64 b) {
    u64 d; asm("add.rn.f32x2 %0, %1, %2;" : "=l"(d) : "l"(a), "l"(b)); return d;
}
__device__ __forceinline__ u64 mul2(u64 a, u64 b) {
    u64 d; asm("mul.rn.f32x2 %0, %1, %2;" : "=l"(d) : "l"(a), "l"(b)); return d;
}
__device__ __forceinline__ void unpack2(u64 v, float& lo, float& hi) {
    asm("mov.b64 {%0,%1}, %2;" : "=f"(lo), "=f"(hi) : "l"(v));
}

// Horizontal window stats for 2 packed column-pairs from 8 contiguous floats.
// Weights c-M with center term skipped; KZ=3: sc = g2-g0 ; KZ=5: sc = (g3+2g4)-(g1+2g0)
template<int KZ>
__device__ __forceinline__ void hstats2(const float* __restrict__ p, bool xfull,
                                        u64 two2, u64 neg12,
                                        u64 (&o0)[2], u64 (&oc)[2], u64 (&o2)[2])
{
    float f[8];
    float4 va = *reinterpret_cast<const float4*>(p);
    f[0]=va.x; f[1]=va.y; f[2]=va.z; f[3]=va.w;
    if (xfull) {
        float4 vb = *reinterpret_cast<const float4*>(p + 4);
        f[4]=vb.x; f[5]=vb.y; f[6]=vb.z; f[7]=vb.w;
    } else { f[4]=0.f; f[5]=0.f; f[6]=0.f; f[7]=0.f; }

    u64 pk[KZ + 2];
#pragma unroll
    for (int c = 0; c < KZ + 2; c++) pk[c] = pack2(f[c], f[c + 1]);

#pragma unroll
    for (int j = 0; j < 2; j++) {
        const int b = j * 2;
        // s0
        u64 s0 = add2(pk[b], pk[b + 1]);
#pragma unroll
        for (int c = 2; c < KZ; c++) s0 = add2(s0, pk[b + c]);
        // s2
        u64 s2 = mul2(pk[b], pk[b]);
#pragma unroll
        for (int c = 1; c < KZ; c++) s2 = fma2(pk[b + c], pk[b + c], s2);
        // sc (antisymmetric weights)
        u64 sc;
        if (KZ == 3) {
            sc = fma2(neg12, pk[b], pk[b + 2]);
        } else { // KZ == 5
            u64 pos = fma2(two2, pk[b + 4], pk[b + 3]);
            u64 neg = fma2(two2, pk[b], pk[b + 1]);
            sc = fma2(neg12, neg, pos);
        }
        o0[j] = s0; oc[j] = sc; o2[j] = s2;
    }
}

template<int KZ, int R, int CG, int CH>
__device__ __forceinline__ float thread_work(const float* __restrict__ src0,
                                             int H, int W, int t)
{
    constexpr int PERIMG = CG * CH;
    const int img   = t / PERIMG;
    int rem         = t - img * PERIMG;
    const int chunk = rem / CG;
    const int cg    = rem - chunk * CG;
    const int x0    = cg * 4;
    const int oy0   = chunk * R;
    const float* __restrict__ src = src0 + (size_t)img * H * W + (size_t)oy0 * W + x0;

    const int outW = W - KZ + 1;
    constexpr float ib = 1.f / (float)(KZ * KZ);
    constexpr float il = 12.f / (float)(KZ * KZ * (KZ * KZ - 1));

    const bool xfull = (x0 + 8) <= W;
    const u64 two2   = pack2(2.f, 2.f);
    const u64 neg12  = pack2(-1.f, -1.f);
    const u64 negib2 = pack2(-ib, -ib);
    const u64 negil2 = pack2(-il, -il);
    u64 mask[2];
#pragma unroll
    for (int j = 0; j < 2; j++)
        mask[j] = pack2((x0 + 2*j)     < outW ? 1.f : 0.f,
                        (x0 + 2*j + 1) < outW ? 1.f : 0.f);

    u64 r0[KZ][2], rc[KZ][2], r2[KZ][2];
    u64 acc[2] = {0ull, 0ull};   // bits of (0.f,0.f)

    const float* p = src;
    // warmup: input rows oy0..oy0+KZ-2 -> slots 0..KZ-2 (no y clamp needed by tiling)
#pragma unroll
    for (int w = 0; w < KZ - 1; w++) {
        hstats2<KZ>(p, xfull, two2, neg12, r0[w], rc[w], r2[w]);
        p += W;
    }

#pragma unroll
    for (int i = 0; i < R; i++) {
        const int slot = (i + KZ - 1) % KZ;
        hstats2<KZ>(p, xfull, two2, neg12, r0[slot], rc[slot], r2[slot]);
        p += W;
#pragma unroll
        for (int j = 0; j < 2; j++) {
            const int s0i = i % KZ, s1i = (i+1) % KZ;
            // vertical combine over ring slots (i..i+KZ-1)%KZ
            u64 S0 = add2(r0[s0i][j], r0[s1i][j]);
            u64 S2 = add2(r2[s0i][j], r2[s1i][j]);
            u64 Sc = add2(rc[s0i][j], rc[s1i][j]);
#pragma unroll
            for (int a = 2; a < KZ; a++) {
                const int s = (i + a) % KZ;
                S0 = add2(S0, r0[s][j]);
                S2 = add2(S2, r2[s][j]);
                Sc = add2(Sc, rc[s][j]);
            }
            u64 Sr;
            if (KZ == 3) {
                Sr = fma2(neg12, r0[i % 3][j], r0[(i + 2) % 3][j]);
            } else {
                u64 pos = fma2(two2, r0[(i + 4) % 5][j], r0[(i + 3) % 5][j]);
                u64 neg = fma2(two2, r0[i % 5][j], r0[(i + 1) % 5][j]);
                Sr = fma2(neg12, neg, pos);
            }
            u64 u  = mul2(Sc, Sc);
            u      = fma2(Sr, Sr, u);
            u64 v  = mul2(S0, S0);
            u64 q  = fma2(v, negib2, S2);
            q      = fma2(u, negil2, q);
            acc[j] = fma2(q, mask[j], acc[j]);
        }
    }
    float a0, a1, b0, b1;
    unpack2(acc[0], a0, a1);
    unpack2(acc[1], b0, b1);
    return (a0 + a1) + (b0 + b1);
}

__global__ void __launch_bounds__(256, 2) fused_kernel(const float* __restrict__ f0,
                                                       const float* __restrict__ f1,
                                                       float* __restrict__ out)
{
    const int tid = threadIdx.x;
    float acc = 0.f;
    double scale;

    if (blockIdx.x < B3_BLOCKS) {
        const int t = blockIdx.x * 256 + tid;          // exact fit
        acc = thread_work<3, 14, 32, 9>(f0, 128, 128, t);
        scale = 1.0 / (32.0 * 126.0 * 126.0);
    } else {
        const int t = (blockIdx.x - B3_BLOCKS) * 256 + tid;
        if (t < T5_THREADS)
            acc = thread_work<5, 14, 63, 18>(f1, 256, 256, t);
        scale = 1.0 / (32.0 * 252.0 * 252.0);
    }

#pragma unroll
    for (int o = 16; o > 0; o >>= 1) acc += __shfl_down_sync(0xffffffffu, acc, o);
    __shared__ float wsum[8];
    __shared__ bool  lastflag;
    if ((tid & 31) == 0) wsum[tid >> 5] = acc;
    __syncthreads();
    if (tid < 32) {
        float v = (tid < 8) ? wsum[tid] : 0.f;
#pragma unroll
        for (int o = 4; o > 0; o >>= 1) v += __shfl_down_sync(0xffffffffu, v, o);
        if (tid == 0) {
            g_part[blockIdx.x] = (double)v * scale;
            __threadfence();
            int done = atomicAdd(&g_count, 1);
            lastflag = (done == NBLOCKS - 1);
        }
    }
    __syncthreads();

    if (lastflag) {
        __threadfence();
        double s = 0.0;
        for (int i = tid; i < NBLOCKS; i += 256) s += g_part[i];
#pragma unroll
        for (int o = 16; o > 0; o >>= 1) s += __shfl_down_sync(0xffffffffu, s, o);
        __shared__ double ws[8];
        if ((tid & 31) == 0) ws[tid >> 5] = s;
        __syncthreads();
        if (tid < 32) {
            double v = (tid < 8) ? ws[tid] : 0.0;
#pragma unroll
            for (int o = 4; o > 0; o >>= 1) v += __shfl_down_sync(0xffffffffu, v, o);
            if (tid == 0) { out[0] = (float)v; g_count = 0; }
        }
    }
}

extern "C" void kernel_launch(void* const* d_in, const int* in_sizes, int n_in,
                              void* d_out, int out_size)
{
    const float* flow0 = (const float*)d_in[0];  // (32,2,128,128)
    const float* flow1 = (const float*)d_in[1];  // (32,2,256,256)
    if (n_in >= 2 && in_sizes[0] > in_sizes[1]) {
        const float* t = flow0; flow0 = flow1; flow1 = t;
    }
    fused_kernel<<<NBLOCKS, 256>>>(flow0, flow1, (float*)d_out);
}